// round 1
// baseline (speedup 1.0000x reference)
#include <cuda_runtime.h>
#include <cuda_fp16.h>
#include <mma.h>

using namespace nvcuda;

// Problem constants
#define B_    8
#define SQ_   1024
#define SK_   1024
#define QDIM  2048
#define KVDIM 1024
#define EDIM  2048
#define H_    16
#define HD_   128

// Scratch (allocation-free: __device__ globals)
__device__ __half g_qh[(size_t)B_ * H_ * SQ_ * HD_];   // [B,H,SQ,HD] fp16, pre-scaled by HD^-0.5
__device__ __half g_kh[(size_t)B_ * H_ * SK_ * HD_];   // [B,H,SK,HD] fp16
__device__ __half g_vh[(size_t)B_ * H_ * SK_ * HD_];   // [B,H,SK,HD] fp16
__device__ float  g_oh[(size_t)B_ * SQ_ * EDIM];       // [B,SQ,E] fp32 (attention output)

// ---------------------------------------------------------------------------
// GEMM: C[M,N] = A[M,K] @ W[N,K]^T + bias, then *out_scale.
// A, W fp32 in global; compute in fp16 wmma with fp32 accum.
// MODE 0: write fp32 row-major [M,N].
// MODE 1: write fp16 head-split: (m=b*SQ+s, n=h*HD+d) -> out[((b*H+h)*SQ+s)*HD+d]
// BM=BN=128, BK=32, 256 threads (8 warps, 4x2; each warp 32x64 = 2x4 wmma tiles)
// ---------------------------------------------------------------------------
template <int MODE>
__global__ void __launch_bounds__(256)
gemm_bias_kernel(const float* __restrict__ A, const float* __restrict__ W,
                 const float* __restrict__ bias, int M, int N, int K,
                 float out_scale, float* __restrict__ outF, __half* __restrict__ outH)
{
    constexpr int BM = 128, BN = 128, BK = 32, LDS = 48; // skewed lds: 96B rows (32B-mult)
    __shared__ __half As[BM][LDS];
    __shared__ __half Bs[BN][LDS];
    __shared__ float  stage[8][256];

    const int tid  = threadIdx.x;
    const int wid  = tid >> 5;
    const int lane = tid & 31;
    const int warpM = wid >> 1;       // 0..3
    const int warpN = wid & 1;        // 0..1
    const int bm0 = blockIdx.y * BM;
    const int bn0 = blockIdx.x * BN;

    wmma::fragment<wmma::accumulator, 16, 16, 16, float> acc[2][4];
#pragma unroll
    for (int i = 0; i < 2; i++)
#pragma unroll
        for (int j = 0; j < 4; j++) wmma::fill_fragment(acc[i][j], 0.0f);

    for (int k0 = 0; k0 < K; k0 += BK) {
        // Load & convert tiles: 128x32 fp32 each, 1024 float4 per tile, 4 per thread
#pragma unroll
        for (int it = 0; it < 4; it++) {
            int slot = it * 256 + tid;
            int row  = slot >> 3;      // 8 float4 per row
            int c4   = slot & 7;
            float4 fa = *(const float4*)(A + (size_t)(bm0 + row) * K + k0 + c4 * 4);
            *(__half2*)&As[row][c4 * 4]     = __floats2half2_rn(fa.x, fa.y);
            *(__half2*)&As[row][c4 * 4 + 2] = __floats2half2_rn(fa.z, fa.w);
            float4 fb = *(const float4*)(W + (size_t)(bn0 + row) * K + k0 + c4 * 4);
            *(__half2*)&Bs[row][c4 * 4]     = __floats2half2_rn(fb.x, fb.y);
            *(__half2*)&Bs[row][c4 * 4 + 2] = __floats2half2_rn(fb.z, fb.w);
        }
        __syncthreads();

#pragma unroll
        for (int kk = 0; kk < 2; kk++) {
            wmma::fragment<wmma::matrix_a, 16, 16, 16, __half, wmma::row_major> af[2];
            wmma::fragment<wmma::matrix_b, 16, 16, 16, __half, wmma::col_major> bf[4];
#pragma unroll
            for (int i = 0; i < 2; i++)
                wmma::load_matrix_sync(af[i], &As[warpM * 32 + i * 16][kk * 16], LDS);
#pragma unroll
            for (int j = 0; j < 4; j++)
                wmma::load_matrix_sync(bf[j], &Bs[warpN * 64 + j * 16][kk * 16], LDS);
#pragma unroll
            for (int i = 0; i < 2; i++)
#pragma unroll
                for (int j = 0; j < 4; j++)
                    wmma::mma_sync(acc[i][j], af[i], bf[j], acc[i][j]);
        }
        __syncthreads();
    }

    // Epilogue: per-fragment staging through smem (no reliance on fragment layout)
#pragma unroll
    for (int i = 0; i < 2; i++) {
#pragma unroll
        for (int j = 0; j < 4; j++) {
            wmma::store_matrix_sync(stage[wid], acc[i][j], 16, wmma::mem_row_major);
            __syncwarp();
            int m0 = bm0 + warpM * 32 + i * 16;
            int n0 = bn0 + warpN * 64 + j * 16;
#pragma unroll
            for (int e = lane; e < 256; e += 32) {
                int r = e >> 4, c = e & 15;
                int m = m0 + r, n = n0 + c;
                float v = (stage[wid][e] + bias[n]) * out_scale;
                if (MODE == 0) {
                    outF[(size_t)m * N + n] = v;
                } else {
                    int b = m / SQ_, s = m % SQ_;
                    int h = n / HD_, d = n % HD_;
                    outH[(((size_t)b * H_ + h) * SQ_ + s) * HD_ + d] = __float2half(v);
                }
            }
            __syncwarp();
        }
    }
}

// ---------------------------------------------------------------------------
// Attention: two-pass flash per (b,h,q-tile of 64). SK streamed in 64-key tiles.
// Pass 1: softmax stats (m, l). Pass 2: O += exp(S-m)/l @ V accumulated in
// wmma fragments (no per-row rescale needed since stats are final).
// Block: 256 threads (8 warps).
// ---------------------------------------------------------------------------
struct AttnSmem {
    __half Qs[64][144];   // 18432 B (288B rows, 32B-mult)
    __half Ks[64][144];   // 18432
    __half Vs[64][144];   // 18432
    float  Ss[64][72];    // 18432
    __half Ps[64][80];    // 10240 (160B rows)
    float  mr[64];
    float  lr[64];
};

__global__ void __launch_bounds__(256)
attn_kernel(const int* __restrict__ mask)
{
    extern __shared__ char smem_raw[];
    AttnSmem& sm = *reinterpret_cast<AttnSmem*>(smem_raw);

    const int tid  = threadIdx.x;
    const int wid  = tid >> 5;
    const int q0   = blockIdx.x * 64;
    const int bh   = blockIdx.y;           // b*H + h
    const int b    = bh / H_;
    const int h    = bh % H_;

    const int warpM = wid >> 1;            // 0..3 (16-row slab)
    const int warpN = wid & 1;             // 0..1
    const int row   = tid >> 2;            // 0..63 (stats/P ownership)
    const int sub   = tid & 3;             // 4 threads per row, 16 cols each

    // Load Q tile (64x128 half), scale already folded in projection
    {
        const __half* qbase = g_qh + ((size_t)bh * SQ_ + q0) * HD_;
#pragma unroll
        for (int it = 0; it < 4; it++) {
            int slot = it * 256 + tid;
            int r = slot >> 4, c8 = slot & 15;
            *(int4*)&sm.Qs[r][c8 * 8] = *(const int4*)(qbase + r * HD_ + c8 * 8);
        }
    }
    if (tid < 64) { sm.mr[tid] = -1e30f; sm.lr[tid] = 0.0f; }
    __syncthreads();

    const __half* kroot = g_kh + (size_t)bh * SK_ * HD_;
    const __half* vroot = g_vh + (size_t)bh * SK_ * HD_;
    const int* mrowbase = mask + (size_t)(b * SQ_ + q0 + row) * SK_ + sub * 16;

    // ---------------- PASS 1: stats ----------------
    for (int j = 0; j < SK_ / 64; j++) {
        const __half* kbase = kroot + (size_t)j * 64 * HD_;
#pragma unroll
        for (int it = 0; it < 4; it++) {
            int slot = it * 256 + tid;
            int r = slot >> 4, c8 = slot & 15;
            *(int4*)&sm.Ks[r][c8 * 8] = *(const int4*)(kbase + r * HD_ + c8 * 8);
        }
        __syncthreads();

        // S = Q @ K^T (64x64): each warp 16x32
        {
            wmma::fragment<wmma::accumulator, 16, 16, 16, float> accs[2];
            wmma::fill_fragment(accs[0], 0.0f);
            wmma::fill_fragment(accs[1], 0.0f);
#pragma unroll
            for (int kk = 0; kk < 8; kk++) {
                wmma::fragment<wmma::matrix_a, 16, 16, 16, __half, wmma::row_major> af;
                wmma::load_matrix_sync(af, &sm.Qs[warpM * 16][kk * 16], 144);
#pragma unroll
                for (int nn = 0; nn < 2; nn++) {
                    wmma::fragment<wmma::matrix_b, 16, 16, 16, __half, wmma::col_major> bf;
                    wmma::load_matrix_sync(bf, &sm.Ks[warpN * 32 + nn * 16][kk * 16], 144);
                    wmma::mma_sync(accs[nn], af, bf, accs[nn]);
                }
            }
#pragma unroll
            for (int nn = 0; nn < 2; nn++)
                wmma::store_matrix_sync(&sm.Ss[warpM * 16][warpN * 32 + nn * 16], accs[nn],
                                        72, wmma::mem_row_major);
        }
        __syncthreads();

        // stats update for this tile
        {
            const int* mptr = mrowbase + j * 64;
            float m_old = sm.mr[row];
            float sv[16];
            float tmax = -1e30f;
#pragma unroll
            for (int u4 = 0; u4 < 4; u4++) {
                int4 mv = *(const int4*)(mptr + u4 * 4);
                int mi[4] = {mv.x, mv.y, mv.z, mv.w};
#pragma unroll
                for (int q = 0; q < 4; q++) {
                    float s = sm.Ss[row][sub * 16 + u4 * 4 + q];
                    s = (mi[q] == 0) ? -1e10f : s;
                    sv[u4 * 4 + q] = s;
                    tmax = fmaxf(tmax, s);
                }
            }
            tmax = fmaxf(tmax, __shfl_xor_sync(0xffffffffu, tmax, 1));
            tmax = fmaxf(tmax, __shfl_xor_sync(0xffffffffu, tmax, 2));
            float m_new = fmaxf(m_old, tmax);
            float ps = 0.0f;
#pragma unroll
            for (int u = 0; u < 16; u++) ps += __expf(sv[u] - m_new);
            ps += __shfl_xor_sync(0xffffffffu, ps, 1);
            ps += __shfl_xor_sync(0xffffffffu, ps, 2);
            if (sub == 0) {
                sm.lr[row] = sm.lr[row] * __expf(m_old - m_new) + ps;
                sm.mr[row] = m_new;
            }
        }
        __syncthreads();
    }

    // ---------------- PASS 2: O = softmax(S) @ V ----------------
    wmma::fragment<wmma::accumulator, 16, 16, 16, float> acco[4];
#pragma unroll
    for (int nn = 0; nn < 4; nn++) wmma::fill_fragment(acco[nn], 0.0f);

    for (int j = 0; j < SK_ / 64; j++) {
        const __half* kbase = kroot + (size_t)j * 64 * HD_;
        const __half* vbase = vroot + (size_t)j * 64 * HD_;
#pragma unroll
        for (int it = 0; it < 4; it++) {
            int slot = it * 256 + tid;
            int r = slot >> 4, c8 = slot & 15;
            *(int4*)&sm.Ks[r][c8 * 8] = *(const int4*)(kbase + r * HD_ + c8 * 8);
            *(int4*)&sm.Vs[r][c8 * 8] = *(const int4*)(vbase + r * HD_ + c8 * 8);
        }
        __syncthreads();

        // S tile (same as pass 1)
        {
            wmma::fragment<wmma::accumulator, 16, 16, 16, float> accs[2];
            wmma::fill_fragment(accs[0], 0.0f);
            wmma::fill_fragment(accs[1], 0.0f);
#pragma unroll
            for (int kk = 0; kk < 8; kk++) {
                wmma::fragment<wmma::matrix_a, 16, 16, 16, __half, wmma::row_major> af;
                wmma::load_matrix_sync(af, &sm.Qs[warpM * 16][kk * 16], 144);
#pragma unroll
                for (int nn = 0; nn < 2; nn++) {
                    wmma::fragment<wmma::matrix_b, 16, 16, 16, __half, wmma::col_major> bf;
                    wmma::load_matrix_sync(bf, &sm.Ks[warpN * 32 + nn * 16][kk * 16], 144);
                    wmma::mma_sync(accs[nn], af, bf, accs[nn]);
                }
            }
#pragma unroll
            for (int nn = 0; nn < 2; nn++)
                wmma::store_matrix_sync(&sm.Ss[warpM * 16][warpN * 32 + nn * 16], accs[nn],
                                        72, wmma::mem_row_major);
        }
        __syncthreads();

        // P = exp(S - m) / l  (final stats; masked entries re-applied)
        {
            const int* mptr = mrowbase + j * 64;
            float mfin = sm.mr[row];
            float lfin = sm.lr[row];
            float rl = (lfin > 0.0f) ? (1.0f / lfin) : 0.0f;
#pragma unroll
            for (int u4 = 0; u4 < 4; u4++) {
                int4 mv = *(const int4*)(mptr + u4 * 4);
                int mi[4] = {mv.x, mv.y, mv.z, mv.w};
#pragma unroll
                for (int q = 0; q < 4; q++) {
                    int col = sub * 16 + u4 * 4 + q;
                    float s = sm.Ss[row][col];
                    s = (mi[q] == 0) ? -1e10f : s;
                    float p = __expf(s - mfin) * rl;
                    sm.Ps[row][col] = __float2half(p);
                }
            }
        }
        __syncthreads();

        // O += P @ V : each warp 16x64
#pragma unroll
        for (int kk = 0; kk < 4; kk++) {
            wmma::fragment<wmma::matrix_a, 16, 16, 16, __half, wmma::row_major> af;
            wmma::load_matrix_sync(af, &sm.Ps[warpM * 16][kk * 16], 80);
#pragma unroll
            for (int nn = 0; nn < 4; nn++) {
                wmma::fragment<wmma::matrix_b, 16, 16, 16, __half, wmma::row_major> bf;
                wmma::load_matrix_sync(bf, &sm.Vs[kk * 16][warpN * 64 + nn * 16], 144);
                wmma::mma_sync(acco[nn], af, bf, acco[nn]);
            }
        }
        __syncthreads();
    }

    // Store O tile to g_oh [B,SQ,E] fp32: (s, d) -> (b*SQ+s)*E + h*HD + d
#pragma unroll
    for (int nn = 0; nn < 4; nn++) {
        float* optr = g_oh + (size_t)(b * SQ_ + q0 + warpM * 16) * EDIM
                    + h * HD_ + warpN * 64 + nn * 16;
        wmma::store_matrix_sync(optr, acco[nn], EDIM, wmma::mem_row_major);
    }
}

// ---------------------------------------------------------------------------
extern "C" void kernel_launch(void* const* d_in, const int* in_sizes, int n_in,
                              void* d_out, int out_size)
{
    (void)in_sizes; (void)n_in; (void)out_size;
    const float* query = (const float*)d_in[0];
    const float* key   = (const float*)d_in[1];
    const float* value = (const float*)d_in[2];
    const int*   amask = (const int*)d_in[3];
    const float* Wq    = (const float*)d_in[4];
    const float* bq    = (const float*)d_in[5];
    const float* Wk    = (const float*)d_in[6];
    const float* bk    = (const float*)d_in[7];
    const float* Wv    = (const float*)d_in[8];
    const float* bv    = (const float*)d_in[9];
    const float* Wo    = (const float*)d_in[10];
    const float* bo    = (const float*)d_in[11];
    float* out = (float*)d_out;

    __half *qh, *kh, *vh; float* oh;
    cudaGetSymbolAddress((void**)&qh, g_qh);
    cudaGetSymbolAddress((void**)&kh, g_kh);
    cudaGetSymbolAddress((void**)&vh, g_vh);
    cudaGetSymbolAddress((void**)&oh, g_oh);

    cudaFuncSetAttribute(attn_kernel, cudaFuncAttributeMaxDynamicSharedMemorySize,
                         (int)sizeof(AttnSmem));

    const int M = B_ * SQ_;                 // 8192
    const float qscale = 0.08838834764831845f;  // HD^-0.5
    dim3 blk(256);
    dim3 gproj(EDIM / 128, M / 128);        // (16, 64)

    // Projections (fp16 head-split outputs)
    gemm_bias_kernel<1><<<gproj, blk>>>(query, Wq, bq, M, EDIM, QDIM, qscale, nullptr, qh);
    gemm_bias_kernel<1><<<gproj, blk>>>(key,   Wk, bk, M, EDIM, KVDIM, 1.0f,  nullptr, kh);
    gemm_bias_kernel<1><<<gproj, blk>>>(value, Wv, bv, M, EDIM, KVDIM, 1.0f,  nullptr, vh);

    // Attention
    dim3 gattn(SQ_ / 64, B_ * H_);          // (16, 128)
    attn_kernel<<<gattn, blk, sizeof(AttnSmem)>>>(amask);

    // Output projection (fp32 to d_out)
    gemm_bias_kernel<0><<<gproj, blk>>>(oh, Wo, bo, M, EDIM, EDIM, 1.0f, out, nullptr);
}

// round 3
// speedup vs baseline: 1.9617x; 1.9617x over previous
#include <cuda_runtime.h>
#include <cuda_fp16.h>
#include <mma.h>

using namespace nvcuda;

#define B_    8
#define SQ_   1024
#define SK_   1024
#define QDIM  2048
#define KVDIM 1024
#define EDIM  2048
#define H_    16
#define HD_   128

// Scratch (allocation-free: __device__ globals)
__device__ __half g_qh[(size_t)B_ * H_ * SQ_ * HD_];   // [B,H,SQ,HD] fp16 (pre-scaled)
__device__ __half g_kh[(size_t)B_ * H_ * SK_ * HD_];
__device__ __half g_vh[(size_t)B_ * H_ * SK_ * HD_];
__device__ __half g_oh[(size_t)B_ * SQ_ * EDIM];       // attention out, fp16 [B,SQ,E]

// ---------------------------------------------------------------------------
// PTX helpers
// ---------------------------------------------------------------------------
__device__ __forceinline__ unsigned smem_u32(const void* p) {
    return (unsigned)__cvta_generic_to_shared(p);
}
__device__ __forceinline__ void ldm_x4(unsigned* r, unsigned addr) {
    asm volatile("ldmatrix.sync.aligned.m8n8.x4.shared.b16 {%0,%1,%2,%3}, [%4];"
                 : "=r"(r[0]), "=r"(r[1]), "=r"(r[2]), "=r"(r[3]) : "r"(addr));
}
__device__ __forceinline__ void ldm_x4_t(unsigned* r, unsigned addr) {
    asm volatile("ldmatrix.sync.aligned.m8n8.x4.trans.shared.b16 {%0,%1,%2,%3}, [%4];"
                 : "=r"(r[0]), "=r"(r[1]), "=r"(r[2]), "=r"(r[3]) : "r"(addr));
}
__device__ __forceinline__ void mma16816(float* d, const unsigned* a, unsigned b0, unsigned b1) {
    asm volatile("mma.sync.aligned.m16n8k16.row.col.f32.f16.f16.f32 "
                 "{%0,%1,%2,%3}, {%4,%5,%6,%7}, {%8,%9}, {%0,%1,%2,%3};"
                 : "+f"(d[0]), "+f"(d[1]), "+f"(d[2]), "+f"(d[3])
                 : "r"(a[0]), "r"(a[1]), "r"(a[2]), "r"(a[3]), "r"(b0), "r"(b1));
}
__device__ __forceinline__ void cp16(unsigned saddr, const void* g) {
    asm volatile("cp.async.cg.shared.global [%0], [%1], 16;" :: "r"(saddr), "l"(g) : "memory");
}
__device__ __forceinline__ void cp_commit() {
    asm volatile("cp.async.commit_group;" ::: "memory");
}
__device__ __forceinline__ unsigned pack_h2(float a, float b) {
    __half2 h = __floats2half2_rn(a, b);
    return *reinterpret_cast<unsigned*>(&h);
}

// ---------------------------------------------------------------------------
// GEMM: C[M,N] = A[M,K] @ W[N,K]^T + bias, *out_scale.
// TA = float or __half for A; W fp32. Double-buffered smem, register prefetch.
// MODE 0: fp32 row-major out. MODE 1: fp16 head-split out.
// ---------------------------------------------------------------------------
template <int MODE, typename TA>
__global__ void __launch_bounds__(256)
gemm_bias_kernel(const TA* __restrict__ A, const float* __restrict__ W,
                 const float* __restrict__ bias, int M, int N, int K,
                 float out_scale, float* __restrict__ outF, __half* __restrict__ outH)
{
    constexpr int BM = 128, BN = 128, BK = 32, LDS = 40;
    __shared__ __half As[2][BM * LDS];
    __shared__ __half Bs[2][BN * LDS];

    const int tid  = threadIdx.x;
    const int wid  = tid >> 5;
    const int lane = tid & 31;
    const int warpM = wid >> 1;   // 0..3
    const int warpN = wid & 1;    // 0..1
    const int bm0 = blockIdx.y * BM;
    const int bn0 = blockIdx.x * BN;

    wmma::fragment<wmma::accumulator, 16, 16, 16, float> acc[2][4];
#pragma unroll
    for (int i = 0; i < 2; i++)
#pragma unroll
        for (int j = 0; j < 4; j++) wmma::fill_fragment(acc[i][j], 0.0f);

    const int T = K / BK;
    float4 rb[4];
    float4 raf[4];
    int4   rah[2];

    auto LDG = [&](int k0) {
#pragma unroll
        for (int it = 0; it < 4; it++) {
            int slot = it * 256 + tid, row = slot >> 3, c4 = slot & 7;
            rb[it] = *(const float4*)(W + (size_t)(bn0 + row) * K + k0 + c4 * 4);
        }
        if constexpr (sizeof(TA) == 4) {
#pragma unroll
            for (int it = 0; it < 4; it++) {
                int slot = it * 256 + tid, row = slot >> 3, c4 = slot & 7;
                raf[it] = *(const float4*)((const float*)A + (size_t)(bm0 + row) * K + k0 + c4 * 4);
            }
        } else {
#pragma unroll
            for (int it = 0; it < 2; it++) {
                int slot = it * 256 + tid, row = slot >> 2, c8 = slot & 3;
                rah[it] = *(const int4*)((const __half*)A + (size_t)(bm0 + row) * K + k0 + c8 * 8);
            }
        }
    };
    auto STS = [&](int buf) {
#pragma unroll
        for (int it = 0; it < 4; it++) {
            int slot = it * 256 + tid, row = slot >> 3, c4 = slot & 7;
            __half* bp = &Bs[buf][row * LDS + c4 * 4];
            *(__half2*)bp       = __floats2half2_rn(rb[it].x, rb[it].y);
            *(__half2*)(bp + 2) = __floats2half2_rn(rb[it].z, rb[it].w);
        }
        if constexpr (sizeof(TA) == 4) {
#pragma unroll
            for (int it = 0; it < 4; it++) {
                int slot = it * 256 + tid, row = slot >> 3, c4 = slot & 7;
                __half* ap = &As[buf][row * LDS + c4 * 4];
                *(__half2*)ap       = __floats2half2_rn(raf[it].x, raf[it].y);
                *(__half2*)(ap + 2) = __floats2half2_rn(raf[it].z, raf[it].w);
            }
        } else {
#pragma unroll
            for (int it = 0; it < 2; it++) {
                int slot = it * 256 + tid, row = slot >> 2, c8 = slot & 3;
                *(int4*)&As[buf][row * LDS + c8 * 8] = rah[it];
            }
        }
    };

    LDG(0);
    STS(0);
    __syncthreads();

    for (int t = 0; t < T; t++) {
        if (t + 1 < T) LDG((t + 1) * BK);
        const int buf = t & 1;
#pragma unroll
        for (int kk = 0; kk < 2; kk++) {
            wmma::fragment<wmma::matrix_a, 16, 16, 16, __half, wmma::row_major> af[2];
            wmma::fragment<wmma::matrix_b, 16, 16, 16, __half, wmma::col_major> bf[4];
#pragma unroll
            for (int i = 0; i < 2; i++)
                wmma::load_matrix_sync(af[i], &As[buf][(warpM * 32 + i * 16) * LDS + kk * 16], LDS);
#pragma unroll
            for (int j = 0; j < 4; j++)
                wmma::load_matrix_sync(bf[j], &Bs[buf][(warpN * 64 + j * 16) * LDS + kk * 16], LDS);
#pragma unroll
            for (int i = 0; i < 2; i++)
#pragma unroll
                for (int j = 0; j < 4; j++)
                    wmma::mma_sync(acc[i][j], af[i], bf[j], acc[i][j]);
        }
        if (t + 1 < T) STS((t + 1) & 1);
        __syncthreads();
    }

    // Epilogue: stage each fragment through smem (alias As, now free)
    float* stage = reinterpret_cast<float*>(&As[0][0]) + wid * 256;
#pragma unroll
    for (int i = 0; i < 2; i++) {
#pragma unroll
        for (int j = 0; j < 4; j++) {
            wmma::store_matrix_sync(stage, acc[i][j], 16, wmma::mem_row_major);
            __syncwarp();
            int m0 = bm0 + warpM * 32 + i * 16;
            int n0 = bn0 + warpN * 64 + j * 16;
#pragma unroll
            for (int e = lane; e < 256; e += 32) {
                int r = e >> 4, c = e & 15;
                int m = m0 + r, n = n0 + c;
                float v = (stage[e] + bias[n]) * out_scale;
                if (MODE == 0) {
                    outF[(size_t)m * N + n] = v;
                } else {
                    int b = m / SQ_, s = m % SQ_;
                    int h = n / HD_, d = n % HD_;
                    outH[(((size_t)b * H_ + h) * SQ_ + s) * HD_ + d] = __float2half(v);
                }
            }
            __syncwarp();
        }
    }
}

// ---------------------------------------------------------------------------
// Single-pass FlashAttention-2. Block = 128 threads (4 warps), Q tile = 64
// (16 rows per warp), KV streamed in 64-key tiles, cp.async double-buffered.
// S/P live in registers (mma.m16n8k16 fragments); online softmax.
// ---------------------------------------------------------------------------
#define SST 136   // smem row stride in halfs (272B: conflict-free for ldmatrix)

__global__ void __launch_bounds__(128, 2)
attn_kernel(const int* __restrict__ mask)
{
    extern __shared__ __half sm[];
    // layout (halfs): Q[64*SST], then buf0: K,V; buf1: K,V (each 64*SST)
    __half* Qs = sm;

    const int tid  = threadIdx.x;
    const int warp = tid >> 5;
    const int lane = tid & 31;
    const int gid  = lane >> 2;
    const int tig  = lane & 3;
    const int q0   = blockIdx.x * 64;
    const int bh   = blockIdx.y;
    const int b    = bh >> 4;
    const int h    = bh & 15;
    const int m0   = warp * 16;

    // Load Q tile (64x128): 1024 int4 slots, 8 iters x 128 threads
    const __half* qbase = g_qh + ((size_t)bh * SQ_ + q0) * HD_;
#pragma unroll
    for (int it = 0; it < 8; it++) {
        int slot = it * 128 + tid;
        int r = slot >> 4, c8 = slot & 15;
        *(int4*)(Qs + r * SST + c8 * 8) = *(const int4*)(qbase + r * HD_ + c8 * 8);
    }

    const __half* kroot = g_kh + (size_t)bh * SK_ * HD_;
    const __half* vroot = g_vh + (size_t)bh * SK_ * HD_;

    auto copy_tile = [&](int j, int buf) {
        const __half* kb = kroot + (size_t)j * 64 * HD_;
        const __half* vb = vroot + (size_t)j * 64 * HD_;
        __half* ks = sm + (1 + 2 * buf) * 64 * SST;
        __half* vs = sm + (2 + 2 * buf) * 64 * SST;
#pragma unroll
        for (int it = 0; it < 8; it++) {
            int slot = it * 128 + tid;
            int r = slot >> 4, c8 = slot & 15;
            cp16(smem_u32(ks + r * SST + c8 * 8), kb + r * HD_ + c8 * 8);
            cp16(smem_u32(vs + r * SST + c8 * 8), vb + r * HD_ + c8 * 8);
        }
    };

    copy_tile(0, 0);
    cp_commit();

    float of[16][4];
#pragma unroll
    for (int i = 0; i < 16; i++)
#pragma unroll
        for (int j = 0; j < 4; j++) of[i][j] = 0.0f;
    float mr0 = -1e30f, mr1 = -1e30f, l0 = 0.0f, l1 = 0.0f;

    const int* mrow0 = mask + (size_t)(b * SQ_ + q0 + m0 + gid) * SK_;
    const int* mrow1 = mrow0 + 8 * SK_;

    // ldmatrix source addresses (lane-dependent parts precomputed)
    const unsigned q_row = m0 + (lane & 15);
    const unsigned q_coff = (lane >> 4) * 8;
    const unsigned kb_row = lane & 15;
    const unsigned kb_coff = ((lane >> 4) & 1) * 8;
    const unsigned vb_coff = (lane >> 4) * 8;

    for (int j = 0; j < 16; j++) {
        const int buf = j & 1;
        if (j < 15) {
            copy_tile(j + 1, buf ^ 1);
            cp_commit();
            asm volatile("cp.async.wait_group 1;" ::: "memory");
        } else {
            asm volatile("cp.async.wait_group 0;" ::: "memory");
        }
        __syncthreads();

        __half* ks = sm + (1 + 2 * buf) * 64 * SST;
        __half* vs = sm + (2 + 2 * buf) * 64 * SST;

        // ---- S = Q @ K^T (16x64 per warp, fragments in registers) ----
        float sfr[8][4];
#pragma unroll
        for (int nt = 0; nt < 8; nt++)
#pragma unroll
            for (int c = 0; c < 4; c++) sfr[nt][c] = 0.0f;

#pragma unroll
        for (int kt = 0; kt < 8; kt++) {
            unsigned a[4];
            ldm_x4(a, smem_u32(Qs + q_row * SST + kt * 16 + q_coff));
#pragma unroll
            for (int dnt = 0; dnt < 4; dnt++) {
                unsigned bb[4];
                // bb: {keys0-7 x dlo, keys8-15 x dlo, keys0-7 x dhi, keys8-15 x dhi}
                ldm_x4(bb, smem_u32(ks + (dnt * 16 + kb_row) * SST + kt * 16 + kb_coff));
                // B operand pairs: {k-lo, k-hi} per n-tile -> {bb0,bb2} and {bb1,bb3}
                mma16816(sfr[2 * dnt],     a, bb[0], bb[2]);
                mma16816(sfr[2 * dnt + 1], a, bb[1], bb[3]);
            }
        }

        // ---- mask + online softmax (registers) ----
        const int key0 = j * 64;
        float mx0 = -1e30f, mx1 = -1e30f;
#pragma unroll
        for (int nt = 0; nt < 8; nt++) {
            int off = key0 + nt * 8 + tig * 2;
            int2 mv0 = *(const int2*)(mrow0 + off);
            int2 mv1 = *(const int2*)(mrow1 + off);
            if (mv0.x == 0) sfr[nt][0] = -1e10f;
            if (mv0.y == 0) sfr[nt][1] = -1e10f;
            if (mv1.x == 0) sfr[nt][2] = -1e10f;
            if (mv1.y == 0) sfr[nt][3] = -1e10f;
            mx0 = fmaxf(mx0, fmaxf(sfr[nt][0], sfr[nt][1]));
            mx1 = fmaxf(mx1, fmaxf(sfr[nt][2], sfr[nt][3]));
        }
        mx0 = fmaxf(mx0, __shfl_xor_sync(0xffffffffu, mx0, 1));
        mx0 = fmaxf(mx0, __shfl_xor_sync(0xffffffffu, mx0, 2));
        mx1 = fmaxf(mx1, __shfl_xor_sync(0xffffffffu, mx1, 1));
        mx1 = fmaxf(mx1, __shfl_xor_sync(0xffffffffu, mx1, 2));

        float mn0 = fmaxf(mr0, mx0), mn1 = fmaxf(mr1, mx1);
        float al0 = __expf(mr0 - mn0), al1 = __expf(mr1 - mn1);
        mr0 = mn0; mr1 = mn1;

        unsigned ph[8][2];
        float s0 = 0.0f, s1 = 0.0f;
#pragma unroll
        for (int nt = 0; nt < 8; nt++) {
            float p0 = __expf(sfr[nt][0] - mn0);
            float p1 = __expf(sfr[nt][1] - mn0);
            float p2 = __expf(sfr[nt][2] - mn1);
            float p3 = __expf(sfr[nt][3] - mn1);
            s0 += p0 + p1; s1 += p2 + p3;
            ph[nt][0] = pack_h2(p0, p1);
            ph[nt][1] = pack_h2(p2, p3);
        }
        s0 += __shfl_xor_sync(0xffffffffu, s0, 1);
        s0 += __shfl_xor_sync(0xffffffffu, s0, 2);
        s1 += __shfl_xor_sync(0xffffffffu, s1, 1);
        s1 += __shfl_xor_sync(0xffffffffu, s1, 2);
        l0 = l0 * al0 + s0;
        l1 = l1 * al1 + s1;

#pragma unroll
        for (int nt = 0; nt < 16; nt++) {
            of[nt][0] *= al0; of[nt][1] *= al0;
            of[nt][2] *= al1; of[nt][3] *= al1;
        }

        // ---- O += P @ V ----
#pragma unroll
        for (int kt = 0; kt < 4; kt++) {
            unsigned a[4] = { ph[2 * kt][0], ph[2 * kt][1], ph[2 * kt + 1][0], ph[2 * kt + 1][1] };
#pragma unroll
            for (int dnt = 0; dnt < 8; dnt++) {
                unsigned bb[4];
                // trans-load: bb = {keys0-7 x dlo^T, keys8-15 x dlo^T, ...} ->
                // pairs {bb0,bb1} (d-lo n-tile) and {bb2,bb3} (d-hi) [k = keys]
                ldm_x4_t(bb, smem_u32(vs + (kt * 16 + kb_row) * SST + dnt * 16 + vb_coff));
                mma16816(of[2 * dnt],     a, bb[0], bb[1]);
                mma16816(of[2 * dnt + 1], a, bb[2], bb[3]);
            }
        }
        __syncthreads();
    }

    // ---- epilogue: O/l -> g_oh fp16 [B,SQ,E] ----
    float rl0 = __fdividef(1.0f, l0);
    float rl1 = __fdividef(1.0f, l1);
    __half* orow0 = g_oh + (size_t)(b * SQ_ + q0 + m0 + gid) * EDIM + h * HD_;
    __half* orow1 = orow0 + (size_t)8 * EDIM;
#pragma unroll
    for (int nt = 0; nt < 16; nt++) {
        int c = nt * 8 + tig * 2;
        *(__half2*)(orow0 + c) = __floats2half2_rn(of[nt][0] * rl0, of[nt][1] * rl0);
        *(__half2*)(orow1 + c) = __floats2half2_rn(of[nt][2] * rl1, of[nt][3] * rl1);
    }
}

// ---------------------------------------------------------------------------
extern "C" void kernel_launch(void* const* d_in, const int* in_sizes, int n_in,
                              void* d_out, int out_size)
{
    (void)in_sizes; (void)n_in; (void)out_size;
    const float* query = (const float*)d_in[0];
    const float* key   = (const float*)d_in[1];
    const float* value = (const float*)d_in[2];
    const int*   amask = (const int*)d_in[3];
    const float* Wq    = (const float*)d_in[4];
    const float* bq    = (const float*)d_in[5];
    const float* Wk    = (const float*)d_in[6];
    const float* bk    = (const float*)d_in[7];
    const float* Wv    = (const float*)d_in[8];
    const float* bv    = (const float*)d_in[9];
    const float* Wo    = (const float*)d_in[10];
    const float* bo    = (const float*)d_in[11];
    float* out = (float*)d_out;

    __half *qh, *kh, *vh, *oh;
    cudaGetSymbolAddress((void**)&qh, g_qh);
    cudaGetSymbolAddress((void**)&kh, g_kh);
    cudaGetSymbolAddress((void**)&vh, g_vh);
    cudaGetSymbolAddress((void**)&oh, g_oh);

    const int attn_smem = 5 * 64 * SST * (int)sizeof(__half);  // 87040 B
    cudaFuncSetAttribute(attn_kernel, cudaFuncAttributeMaxDynamicSharedMemorySize, attn_smem);

    const int M = B_ * SQ_;                      // 8192
    const float qscale = 0.08838834764831845f;   // HD^-0.5
    dim3 blk(256);
    dim3 gproj(EDIM / 128, M / 128);             // (16, 64)

    gemm_bias_kernel<1, float><<<gproj, blk>>>(query, Wq, bq, M, EDIM, QDIM, qscale, nullptr, qh);
    gemm_bias_kernel<1, float><<<gproj, blk>>>(key,   Wk, bk, M, EDIM, KVDIM, 1.0f,  nullptr, kh);
    gemm_bias_kernel<1, float><<<gproj, blk>>>(value, Wv, bv, M, EDIM, KVDIM, 1.0f,  nullptr, vh);

    dim3 gattn(SQ_ / 64, B_ * H_);               // (16, 128)
    attn_kernel<<<gattn, dim3(128), attn_smem>>>(amask);

    gemm_bias_kernel<0, __half><<<gproj, blk>>>(oh, Wo, bo, M, EDIM, EDIM, 1.0f, out, nullptr);
}

// round 4
// speedup vs baseline: 2.2770x; 1.1607x over previous
#include <cuda_runtime.h>
#include <cuda_fp16.h>

#define B_    8
#define SQ_   1024
#define SK_   1024
#define QDIM  2048
#define KVDIM 1024
#define EDIM  2048
#define H_    16
#define HD_   128

// Scratch (allocation-free: __device__ globals)
__device__ __half g_qh[(size_t)B_ * H_ * SQ_ * HD_];   // [B,H,SQ,HD] fp16 (pre-scaled)
__device__ __half g_kh[(size_t)B_ * H_ * SK_ * HD_];
__device__ __half g_vh[(size_t)B_ * H_ * SK_ * HD_];
__device__ __half g_oh[(size_t)B_ * SQ_ * EDIM];       // attention out, fp16 [B,SQ,E]
__device__ __half g_x16[33554432];                     // fp16 query|key|value
__device__ __half g_w16[12582912];                     // fp16 Wq|Wk|Wv|Wo

// ---------------------------------------------------------------------------
// PTX helpers
// ---------------------------------------------------------------------------
__device__ __forceinline__ unsigned smem_u32(const void* p) {
    return (unsigned)__cvta_generic_to_shared(p);
}
__device__ __forceinline__ void ldm_x4(unsigned* r, unsigned addr) {
    asm volatile("ldmatrix.sync.aligned.m8n8.x4.shared.b16 {%0,%1,%2,%3}, [%4];"
                 : "=r"(r[0]), "=r"(r[1]), "=r"(r[2]), "=r"(r[3]) : "r"(addr));
}
__device__ __forceinline__ void ldm_x4_t(unsigned* r, unsigned addr) {
    asm volatile("ldmatrix.sync.aligned.m8n8.x4.trans.shared.b16 {%0,%1,%2,%3}, [%4];"
                 : "=r"(r[0]), "=r"(r[1]), "=r"(r[2]), "=r"(r[3]) : "r"(addr));
}
__device__ __forceinline__ void mma16816(float* d, const unsigned* a, unsigned b0, unsigned b1) {
    asm volatile("mma.sync.aligned.m16n8k16.row.col.f32.f16.f16.f32 "
                 "{%0,%1,%2,%3}, {%4,%5,%6,%7}, {%8,%9}, {%0,%1,%2,%3};"
                 : "+f"(d[0]), "+f"(d[1]), "+f"(d[2]), "+f"(d[3])
                 : "r"(a[0]), "r"(a[1]), "r"(a[2]), "r"(a[3]), "r"(b0), "r"(b1));
}
__device__ __forceinline__ void cp16(unsigned saddr, const void* g) {
    asm volatile("cp.async.cg.shared.global [%0], [%1], 16;" :: "r"(saddr), "l"(g) : "memory");
}
__device__ __forceinline__ void cp_commit() {
    asm volatile("cp.async.commit_group;" ::: "memory");
}
template <int N>
__device__ __forceinline__ void cp_wait() {
    asm volatile("cp.async.wait_group %0;" :: "n"(N) : "memory");
}
__device__ __forceinline__ unsigned pack_h2(float a, float b) {
    __half2 h = __floats2half2_rn(a, b);
    return *reinterpret_cast<unsigned*>(&h);
}

// ---------------------------------------------------------------------------
// fp32 -> fp16 convert, 8 elts/thread
// ---------------------------------------------------------------------------
__global__ void cvt_kernel(const float* __restrict__ in, __half* __restrict__ out, int n)
{
    int i = (blockIdx.x * blockDim.x + threadIdx.x) * 8;
    if (i < n) {
        float4 f0 = *(const float4*)(in + i);
        float4 f1 = *(const float4*)(in + i + 4);
        __half2 h[4];
        h[0] = __floats2half2_rn(f0.x, f0.y);
        h[1] = __floats2half2_rn(f0.z, f0.w);
        h[2] = __floats2half2_rn(f1.x, f1.y);
        h[3] = __floats2half2_rn(f1.z, f1.w);
        *(int4*)(out + i) = *(int4*)h;
    }
}

// ---------------------------------------------------------------------------
// GEMM (all fp16 in): C[M,N] = A[M,K] @ W[N,K]^T + bias, *out_scale.
// cp.async 3-stage pipeline, BK=64, raw mma.m16n8k16.
// 256 threads, 8 warps = 4(M) x 2(N), each warp 32x64.
// MODE 0: fp32 row-major out. MODE 1: fp16 head-split out.
// ---------------------------------------------------------------------------
#define G_LDS   72                         // halfs per smem row (64 + 8 pad)
#define G_STAGE (256 * G_LDS)              // halfs per stage (A 128 rows + B 128 rows)

template <int MODE>
__global__ void __launch_bounds__(256)
gemm_h_kernel(const __half* __restrict__ A, const __half* __restrict__ W,
              const float* __restrict__ bias, int M, int N, int K,
              float out_scale, float* __restrict__ outF, __half* __restrict__ outH)
{
    constexpr int BK = 64, S = 3;
    extern __shared__ __half smem[];       // S * G_STAGE halfs

    const int tid  = threadIdx.x;
    const int wid  = tid >> 5;
    const int lane = tid & 31;
    const int warpM = wid >> 1;            // 0..3
    const int warpN = wid & 1;             // 0..1
    const int bm0 = blockIdx.y * 128;
    const int bn0 = blockIdx.x * 128;
    const int T = K / BK;

    const int cp_row = tid >> 3;           // 0..31
    const int cp_c8  = (tid & 7) * 8;

    auto copy_tile = [&](int t, int s) {
        __half* sA = smem + s * G_STAGE;
        __half* sB = sA + 128 * G_LDS;
        const __half* ga = A + (size_t)bm0 * K + t * BK;
        const __half* gw = W + (size_t)bn0 * K + t * BK;
#pragma unroll
        for (int it = 0; it < 4; it++) {
            int row = it * 32 + cp_row;
            cp16(smem_u32(sA + row * G_LDS + cp_c8), ga + (size_t)row * K + cp_c8);
            cp16(smem_u32(sB + row * G_LDS + cp_c8), gw + (size_t)row * K + cp_c8);
        }
    };

    float acc[2][8][4];
#pragma unroll
    for (int i = 0; i < 2; i++)
#pragma unroll
        for (int j = 0; j < 8; j++)
#pragma unroll
            for (int c = 0; c < 4; c++) acc[i][j][c] = 0.0f;

    // ldmatrix lane addressing
    const int a_row = warpM * 32 + (lane & 15);
    const int a_co  = (lane >> 4) * 8;
    const int b_row = warpN * 64 + (lane & 15);
    const int b_co  = ((lane >> 4) & 1) * 8;

    // prologue: stage 0,1
    copy_tile(0, 0); cp_commit();
    copy_tile(1, 1); cp_commit();

    for (int t = 0; t < T; t++) {
        cp_wait<S - 2>();
        __syncthreads();
        if (t + S - 1 < T) copy_tile(t + S - 1, (t + S - 1) % S);
        cp_commit();

        const __half* sA = smem + (t % S) * G_STAGE;
        const __half* sB = sA + 128 * G_LDS;
#pragma unroll
        for (int kt = 0; kt < 4; kt++) {
            unsigned a0[4], a1[4];
            ldm_x4(a0, smem_u32(sA + (a_row)      * G_LDS + kt * 16 + a_co));
            ldm_x4(a1, smem_u32(sA + (a_row + 16) * G_LDS + kt * 16 + a_co));
#pragma unroll
            for (int nj = 0; nj < 4; nj++) {
                unsigned bb[4];
                ldm_x4(bb, smem_u32(sB + (b_row + nj * 16) * G_LDS + kt * 16 + b_co));
                mma16816(acc[0][2 * nj],     a0, bb[0], bb[2]);
                mma16816(acc[0][2 * nj + 1], a0, bb[1], bb[3]);
                mma16816(acc[1][2 * nj],     a1, bb[0], bb[2]);
                mma16816(acc[1][2 * nj + 1], a1, bb[1], bb[3]);
            }
        }
    }

    // epilogue: direct global writes from mma accumulator layout
    const int gid = lane >> 2;
    const int tig = lane & 3;
#pragma unroll
    for (int mi = 0; mi < 2; mi++) {
        int m = bm0 + warpM * 32 + mi * 16 + gid;
#pragma unroll
        for (int nj = 0; nj < 8; nj++) {
            int n = bn0 + warpN * 64 + nj * 8 + tig * 2;
            float2 bv = *(const float2*)(bias + n);
            float v0 = (acc[mi][nj][0] + bv.x) * out_scale;
            float v1 = (acc[mi][nj][1] + bv.y) * out_scale;
            float v2 = (acc[mi][nj][2] + bv.x) * out_scale;
            float v3 = (acc[mi][nj][3] + bv.y) * out_scale;
            if (MODE == 0) {
                float2 w0 = {v0, v1}, w1 = {v2, v3};
                *(float2*)(outF + (size_t)m * N + n) = w0;
                *(float2*)(outF + (size_t)(m + 8) * N + n) = w1;
            } else {
                int b = m >> 10, s = m & 1023;
                int h = n >> 7,  d = n & 127;
                __half* p = outH + (((size_t)b * H_ + h) * SQ_ + s) * HD_ + d;
                *(__half2*)p = __floats2half2_rn(v0, v1);
                *(__half2*)(p + 8 * HD_) = __floats2half2_rn(v2, v3);
            }
        }
    }
}

// ---------------------------------------------------------------------------
// Single-pass FlashAttention-2 (verified round 3). 128 threads, 64-q tile,
// 64-key KV tiles cp.async double-buffered, S/P in registers.
// ---------------------------------------------------------------------------
#define SST 136

__global__ void __launch_bounds__(128, 2)
attn_kernel(const int* __restrict__ mask)
{
    extern __shared__ __half sm[];
    __half* Qs = sm;

    const int tid  = threadIdx.x;
    const int warp = tid >> 5;
    const int lane = tid & 31;
    const int gid  = lane >> 2;
    const int tig  = lane & 3;
    const int q0   = blockIdx.x * 64;
    const int bh   = blockIdx.y;
    const int b    = bh >> 4;
    const int h    = bh & 15;
    const int m0   = warp * 16;

    const __half* qbase = g_qh + ((size_t)bh * SQ_ + q0) * HD_;
#pragma unroll
    for (int it = 0; it < 8; it++) {
        int slot = it * 128 + tid;
        int r = slot >> 4, c8 = slot & 15;
        *(int4*)(Qs + r * SST + c8 * 8) = *(const int4*)(qbase + r * HD_ + c8 * 8);
    }

    const __half* kroot = g_kh + (size_t)bh * SK_ * HD_;
    const __half* vroot = g_vh + (size_t)bh * SK_ * HD_;

    auto copy_tile = [&](int j, int buf) {
        const __half* kb = kroot + (size_t)j * 64 * HD_;
        const __half* vb = vroot + (size_t)j * 64 * HD_;
        __half* ks = sm + (1 + 2 * buf) * 64 * SST;
        __half* vs = sm + (2 + 2 * buf) * 64 * SST;
#pragma unroll
        for (int it = 0; it < 8; it++) {
            int slot = it * 128 + tid;
            int r = slot >> 4, c8 = slot & 15;
            cp16(smem_u32(ks + r * SST + c8 * 8), kb + r * HD_ + c8 * 8);
            cp16(smem_u32(vs + r * SST + c8 * 8), vb + r * HD_ + c8 * 8);
        }
    };

    copy_tile(0, 0);
    cp_commit();

    float of[16][4];
#pragma unroll
    for (int i = 0; i < 16; i++)
#pragma unroll
        for (int j = 0; j < 4; j++) of[i][j] = 0.0f;
    float mr0 = -1e30f, mr1 = -1e30f, l0 = 0.0f, l1 = 0.0f;

    const int* mrow0 = mask + (size_t)(b * SQ_ + q0 + m0 + gid) * SK_;
    const int* mrow1 = mrow0 + 8 * SK_;

    const unsigned q_row = m0 + (lane & 15);
    const unsigned q_coff = (lane >> 4) * 8;
    const unsigned kb_row = lane & 15;
    const unsigned kb_coff = ((lane >> 4) & 1) * 8;
    const unsigned vb_coff = (lane >> 4) * 8;

    for (int j = 0; j < 16; j++) {
        const int buf = j & 1;
        if (j < 15) {
            copy_tile(j + 1, buf ^ 1);
            cp_commit();
            cp_wait<1>();
        } else {
            cp_wait<0>();
        }
        __syncthreads();

        __half* ks = sm + (1 + 2 * buf) * 64 * SST;
        __half* vs = sm + (2 + 2 * buf) * 64 * SST;

        float sfr[8][4];
#pragma unroll
        for (int nt = 0; nt < 8; nt++)
#pragma unroll
            for (int c = 0; c < 4; c++) sfr[nt][c] = 0.0f;

#pragma unroll
        for (int kt = 0; kt < 8; kt++) {
            unsigned a[4];
            ldm_x4(a, smem_u32(Qs + q_row * SST + kt * 16 + q_coff));
#pragma unroll
            for (int dnt = 0; dnt < 4; dnt++) {
                unsigned bb[4];
                ldm_x4(bb, smem_u32(ks + (dnt * 16 + kb_row) * SST + kt * 16 + kb_coff));
                mma16816(sfr[2 * dnt],     a, bb[0], bb[2]);
                mma16816(sfr[2 * dnt + 1], a, bb[1], bb[3]);
            }
        }

        const int key0 = j * 64;
        float mx0 = -1e30f, mx1 = -1e30f;
#pragma unroll
        for (int nt = 0; nt < 8; nt++) {
            int off = key0 + nt * 8 + tig * 2;
            int2 mv0 = *(const int2*)(mrow0 + off);
            int2 mv1 = *(const int2*)(mrow1 + off);
            if (mv0.x == 0) sfr[nt][0] = -1e10f;
            if (mv0.y == 0) sfr[nt][1] = -1e10f;
            if (mv1.x == 0) sfr[nt][2] = -1e10f;
            if (mv1.y == 0) sfr[nt][3] = -1e10f;
            mx0 = fmaxf(mx0, fmaxf(sfr[nt][0], sfr[nt][1]));
            mx1 = fmaxf(mx1, fmaxf(sfr[nt][2], sfr[nt][3]));
        }
        mx0 = fmaxf(mx0, __shfl_xor_sync(0xffffffffu, mx0, 1));
        mx0 = fmaxf(mx0, __shfl_xor_sync(0xffffffffu, mx0, 2));
        mx1 = fmaxf(mx1, __shfl_xor_sync(0xffffffffu, mx1, 1));
        mx1 = fmaxf(mx1, __shfl_xor_sync(0xffffffffu, mx1, 2));

        float mn0 = fmaxf(mr0, mx0), mn1 = fmaxf(mr1, mx1);
        float al0 = __expf(mr0 - mn0), al1 = __expf(mr1 - mn1);
        mr0 = mn0; mr1 = mn1;

        unsigned ph[8][2];
        float s0 = 0.0f, s1 = 0.0f;
#pragma unroll
        for (int nt = 0; nt < 8; nt++) {
            float p0 = __expf(sfr[nt][0] - mn0);
            float p1 = __expf(sfr[nt][1] - mn0);
            float p2 = __expf(sfr[nt][2] - mn1);
            float p3 = __expf(sfr[nt][3] - mn1);
            s0 += p0 + p1; s1 += p2 + p3;
            ph[nt][0] = pack_h2(p0, p1);
            ph[nt][1] = pack_h2(p2, p3);
        }
        s0 += __shfl_xor_sync(0xffffffffu, s0, 1);
        s0 += __shfl_xor_sync(0xffffffffu, s0, 2);
        s1 += __shfl_xor_sync(0xffffffffu, s1, 1);
        s1 += __shfl_xor_sync(0xffffffffu, s1, 2);
        l0 = l0 * al0 + s0;
        l1 = l1 * al1 + s1;

        // warp-uniform skip: no row in this warp saw a new max -> al == 1
        if (!__all_sync(0xffffffffu, (al0 == 1.0f) & (al1 == 1.0f))) {
#pragma unroll
            for (int nt = 0; nt < 16; nt++) {
                of[nt][0] *= al0; of[nt][1] *= al0;
                of[nt][2] *= al1; of[nt][3] *= al1;
            }
        }

#pragma unroll
        for (int kt = 0; kt < 4; kt++) {
            unsigned a[4] = { ph[2 * kt][0], ph[2 * kt][1], ph[2 * kt + 1][0], ph[2 * kt + 1][1] };
#pragma unroll
            for (int dnt = 0; dnt < 8; dnt++) {
                unsigned bb[4];
                ldm_x4_t(bb, smem_u32(vs + (kt * 16 + kb_row) * SST + dnt * 16 + vb_coff));
                mma16816(of[2 * dnt],     a, bb[0], bb[1]);
                mma16816(of[2 * dnt + 1], a, bb[2], bb[3]);
            }
        }
        __syncthreads();
    }

    float rl0 = __fdividef(1.0f, l0);
    float rl1 = __fdividef(1.0f, l1);
    __half* orow0 = g_oh + (size_t)(b * SQ_ + q0 + m0 + gid) * EDIM + h * HD_;
    __half* orow1 = orow0 + (size_t)8 * EDIM;
#pragma unroll
    for (int nt = 0; nt < 16; nt++) {
        int c = nt * 8 + tig * 2;
        *(__half2*)(orow0 + c) = __floats2half2_rn(of[nt][0] * rl0, of[nt][1] * rl0);
        *(__half2*)(orow1 + c) = __floats2half2_rn(of[nt][2] * rl1, of[nt][3] * rl1);
    }
}

// ---------------------------------------------------------------------------
extern "C" void kernel_launch(void* const* d_in, const int* in_sizes, int n_in,
                              void* d_out, int out_size)
{
    (void)in_sizes; (void)n_in; (void)out_size;
    const float* query = (const float*)d_in[0];
    const float* key   = (const float*)d_in[1];
    const float* value = (const float*)d_in[2];
    const int*   amask = (const int*)d_in[3];
    const float* Wq    = (const float*)d_in[4];
    const float* bq    = (const float*)d_in[5];
    const float* Wk    = (const float*)d_in[6];
    const float* bk    = (const float*)d_in[7];
    const float* Wv    = (const float*)d_in[8];
    const float* bv    = (const float*)d_in[9];
    const float* Wo    = (const float*)d_in[10];
    const float* bo    = (const float*)d_in[11];
    float* out = (float*)d_out;

    __half *qh, *kh, *vh, *oh, *x16, *w16;
    cudaGetSymbolAddress((void**)&qh, g_qh);
    cudaGetSymbolAddress((void**)&kh, g_kh);
    cudaGetSymbolAddress((void**)&vh, g_vh);
    cudaGetSymbolAddress((void**)&oh, g_oh);
    cudaGetSymbolAddress((void**)&x16, g_x16);
    cudaGetSymbolAddress((void**)&w16, g_w16);

    const int attn_smem = 5 * 64 * SST * (int)sizeof(__half);         // 87040
    const int gemm_smem = 3 * G_STAGE * (int)sizeof(__half);          // 110592
    cudaFuncSetAttribute(attn_kernel, cudaFuncAttributeMaxDynamicSharedMemorySize, attn_smem);
    cudaFuncSetAttribute(gemm_h_kernel<0>, cudaFuncAttributeMaxDynamicSharedMemorySize, gemm_smem);
    cudaFuncSetAttribute(gemm_h_kernel<1>, cudaFuncAttributeMaxDynamicSharedMemorySize, gemm_smem);

    // fp16 scratch offsets
    __half* xq = x16;                      // 16777216
    __half* xk = x16 + 16777216;           //  8388608
    __half* xv = x16 + 25165824;           //  8388608
    __half* wq = w16;                      //  4194304
    __half* wk = w16 + 4194304;            //  2097152
    __half* wv = w16 + 6291456;            //  2097152
    __half* wo = w16 + 8388608;            //  4194304

    // converts
    auto cvt = [&](const float* src, __half* dst, int n) {
        cvt_kernel<<<(n / 8 + 255) / 256, 256>>>(src, dst, n);
    };
    cvt(query, xq, 16777216);
    cvt(key,   xk, 8388608);
    cvt(value, xv, 8388608);
    cvt(Wq, wq, 4194304);
    cvt(Wk, wk, 2097152);
    cvt(Wv, wv, 2097152);
    cvt(Wo, wo, 4194304);

    const int M = B_ * SQ_;                      // 8192
    const float qscale = 0.08838834764831845f;   // HD^-0.5
    dim3 blk(256);
    dim3 gproj(EDIM / 128, M / 128);             // (16, 64)

    gemm_h_kernel<1><<<gproj, blk, gemm_smem>>>(xq, wq, bq, M, EDIM, QDIM, qscale, nullptr, qh);
    gemm_h_kernel<1><<<gproj, blk, gemm_smem>>>(xk, wk, bk, M, EDIM, KVDIM, 1.0f, nullptr, kh);
    gemm_h_kernel<1><<<gproj, blk, gemm_smem>>>(xv, wv, bv, M, EDIM, KVDIM, 1.0f, nullptr, vh);

    dim3 gattn(SQ_ / 64, B_ * H_);               // (16, 128)
    attn_kernel<<<gattn, dim3(128), attn_smem>>>(amask);

    gemm_h_kernel<0><<<gproj, blk, gemm_smem>>>(oh, wo, bo, M, EDIM, EDIM, 1.0f, out, nullptr);
}